// round 14
// baseline (speedup 1.0000x reference)
#include <cuda_runtime.h>
#include <cuda_bf16.h>
#include <cuda_fp16.h>

// Problem constants (fixed shapes from the reference)
#define NMAX 50000
#define EMAX 800000
#define INC  256
#define NHEAD 8
#define CH   32
#define HC   256   // NHEAD*CH

// ---------------- scratch (static device globals; no allocs allowed) -------
__device__ __half   g_xhh[NMAX * HC];           // projected features, fp16
__device__ float    g_asrc[NMAX * NHEAD];       // per-node src logits
__device__ float    g_adst[NMAX * NHEAD];       // per-node dst logits
__device__ float    g_vT[16 * INC];             // folded att vectors [k][i]
__device__ int      g_edges[2 * EMAX];          // converted int32 edge index
__device__ int      g_cnt[NMAX];                // in-degree histogram
__device__ int      g_fill[NMAX];               // scatter fill counters
__device__ int      g_off[NMAX + 1];            // CSR offsets
__device__ int2     g_sedge[EMAX];              // (src, orig edge id) dst-sorted
__device__ int      g_is64;

// ---------------- K0: detect int64 vs int32 edge_index ---------------------
__global__ void k_detect(const int* __restrict__ p, int n_words) {
    __shared__ int s;
    if (threadIdx.x == 0) s = 0;
    __syncthreads();
    int acc = 0;
    for (int i = 1 + 2 * (int)threadIdx.x; i < n_words; i += 2 * blockDim.x)
        acc |= p[i];
    if (acc) atomicOr(&s, 1);
    __syncthreads();
    if (threadIdx.x == 0) g_is64 = (s == 0) ? 1 : 0;
}

// ---------------- K0b: zero histogram + fill counters ----------------------
__global__ void k_zero(int Nn) {
    int i = blockIdx.x * blockDim.x + threadIdx.x;
    if (i < Nn) { g_cnt[i] = 0; g_fill[i] = 0; }
}

// ---------------- K1: convert edge index to int32 + dst histogram ----------
__global__ void k_convert(const void* __restrict__ p, int twoE, int E) {
    int i = blockIdx.x * blockDim.x + threadIdx.x;
    if (i >= twoE) return;
    int v;
    if (g_is64) v = (int)((const long long*)p)[i];
    else        v = ((const int*)p)[i];
    g_edges[i] = v;
    if (i >= E) atomicAdd(&g_cnt[v], 1);   // dst half -> in-degree histogram
}

// ---------------- K1b: fold att vectors through W ---------------------------
// v[i][h]      = sum_c W[i][h][c] * att_src[h][c]   (k = h)
// v[i][h+8]    = sum_c W[i][h][c] * att_dst[h][c]   (k = h+8)
__global__ void k_prew(const float* __restrict__ W,
                       const float* __restrict__ att_src,
                       const float* __restrict__ att_dst) {
    int t = blockIdx.x * blockDim.x + threadIdx.x;
    if (t >= 16 * INC) return;
    int i = t >> 4;          // input channel 0..255
    int k = t & 15;          // output index
    int h = k & 7;
    const float* att = (k < 8) ? att_src : att_dst;
    float s = 0.f;
#pragma unroll
    for (int c = 0; c < CH; c++)
        s += W[(size_t)i * HC + h * CH + c] * att[h * CH + c];
    g_vT[k * INC + i] = s;
}

// ---------------- K1c: logits directly from x (warp per node) --------------
// a_src[n,h] = x[n,:] @ v[:,h] ; exact fp32, independent of the GEMM.
__global__ void k_lg(const float* __restrict__ x, int Nn) {
    int w    = (blockIdx.x * blockDim.x + threadIdx.x) >> 5;
    int lane = threadIdx.x & 31;
    if (w >= Nn) return;
    int cb = lane * 8;
    float4 x0 = __ldg((const float4*)&x[(size_t)w * INC + cb]);
    float4 x1 = __ldg((const float4*)&x[(size_t)w * INC + cb + 4]);
    float s[16];
#pragma unroll
    for (int k = 0; k < 16; k++) {
        float4 v0 = __ldg((const float4*)&g_vT[k * INC + cb]);
        float4 v1 = __ldg((const float4*)&g_vT[k * INC + cb + 4]);
        s[k] = x0.x * v0.x + x0.y * v0.y + x0.z * v0.z + x0.w * v0.w
             + x1.x * v1.x + x1.y * v1.y + x1.z * v1.z + x1.w * v1.w;
    }
#pragma unroll
    for (int k = 0; k < 16; k++) {
#pragma unroll
        for (int o = 16; o > 0; o >>= 1)
            s[k] += __shfl_xor_sync(0xFFFFFFFFu, s[k], o);
    }
    if (lane == 0) {
        *(float4*)&g_asrc[w * NHEAD]     = make_float4(s[0], s[1], s[2], s[3]);
        *(float4*)&g_asrc[w * NHEAD + 4] = make_float4(s[4], s[5], s[6], s[7]);
        *(float4*)&g_adst[w * NHEAD]     = make_float4(s[8], s[9], s[10], s[11]);
        *(float4*)&g_adst[w * NHEAD + 4] = make_float4(s[12], s[13], s[14], s[15]);
    }
}

// ---------------- MMA helpers ----------------------------------------------
__device__ __forceinline__ void ldsm4(unsigned r[4], const void* p) {
    unsigned a = (unsigned)__cvta_generic_to_shared(p);
    asm volatile("ldmatrix.sync.aligned.m8n8.x4.shared.b16 {%0,%1,%2,%3}, [%4];"
                 : "=r"(r[0]), "=r"(r[1]), "=r"(r[2]), "=r"(r[3]) : "r"(a));
}
__device__ __forceinline__ void ldsm4t(unsigned r[4], const void* p) {
    unsigned a = (unsigned)__cvta_generic_to_shared(p);
    asm volatile("ldmatrix.sync.aligned.m8n8.x4.trans.shared.b16 {%0,%1,%2,%3}, [%4];"
                 : "=r"(r[0]), "=r"(r[1]), "=r"(r[2]), "=r"(r[3]) : "r"(a));
}
__device__ __forceinline__ void mma16816(float c[4], const unsigned a[4],
                                         unsigned b0, unsigned b1) {
    asm volatile(
        "mma.sync.aligned.m16n8k16.row.col.f32.bf16.bf16.f32 "
        "{%0,%1,%2,%3}, {%4,%5,%6,%7}, {%8,%9}, {%0,%1,%2,%3};"
        : "+f"(c[0]), "+f"(c[1]), "+f"(c[2]), "+f"(c[3])
        : "r"(a[0]), "r"(a[1]), "r"(a[2]), "r"(a[3]), "r"(b0), "r"(b1));
}
__device__ __forceinline__ void split_bf16(float v, __nv_bfloat16& h, __nv_bfloat16& l) {
    h = __float2bfloat16(v);
    l = __float2bfloat16(v - __bfloat162float(h));
}

// ---------------- K2: xh = x @ W  -- CTA 128x256, 512 thr, bf16 split ------
// 16 warps as 4(M) x 4(N); warp tile 32x64. A read ONCE from DRAM.
// acc = Ah*Bh + Ah*Bl + Al*Bh
#define GBM 128
#define GBK 32
// dynamic smem element offsets (bf16 elements)
#define SAH_OFF 0              // [2][128][40]
#define SAL_OFF 10240
#define SBH_OFF 20480          // [2][32][264]
#define SBL_OFF 37376
#define SMEM_ELEMS 54272       // * 2B = 108544 bytes

__global__ __launch_bounds__(512, 1) void k_gemm(const float* __restrict__ A,
                                                 const float* __restrict__ B,
                                                 int Nn) {
    extern __shared__ __nv_bfloat16 sm[];

    int tid  = threadIdx.x;
    int lane = tid & 31;
    int warp = tid >> 5;
    int wm = warp & 3, wn = warp >> 2;   // 4 x 4 warp grid
    int brow = blockIdx.x * GBM;

    float acc[2][8][4];
#pragma unroll
    for (int i = 0; i < 2; i++)
#pragma unroll
        for (int j = 0; j < 8; j++)
#pragma unroll
            for (int k = 0; k < 4; k++) acc[i][j][k] = 0.f;

    // loader coordinates
    int ar  = tid >> 3;            // A row 0..63 (+q*64)
    int ac  = (tid & 7) * 4;       // A col 0..28
    int brr = tid >> 6;            // B row 0..7 (+q*8)
    int bcc = (tid & 63) * 4;      // B col 0..252

    float4 a4[2], b4[4];

    // prologue: load k0 = 0
#pragma unroll
    for (int q = 0; q < 2; q++) {
        int gr = brow + ar + q * 64;
        a4[q] = make_float4(0.f, 0.f, 0.f, 0.f);
        if (gr < Nn) a4[q] = *(const float4*)&A[(size_t)gr * INC + ac];
    }
#pragma unroll
    for (int q = 0; q < 4; q++)
        b4[q] = *(const float4*)&B[(size_t)(brr + q * 8) * HC + bcc];

#define STORE_TILE(p)                                                          \
    do {                                                                       \
        _Pragma("unroll")                                                      \
        for (int q = 0; q < 2; q++) {                                          \
            int row = ar + q * 64;                                             \
            __nv_bfloat16* pAh = sm + SAH_OFF + (p) * 5120 + row * 40 + ac;    \
            __nv_bfloat16* pAl = sm + SAL_OFF + (p) * 5120 + row * 40 + ac;    \
            float vs[4] = {a4[q].x, a4[q].y, a4[q].z, a4[q].w};                \
            _Pragma("unroll")                                                  \
            for (int u = 0; u < 4; u += 2) {                                   \
                __nv_bfloat16 h0, l0, h1, l1;                                  \
                split_bf16(vs[u], h0, l0);                                     \
                split_bf16(vs[u + 1], h1, l1);                                 \
                *(__nv_bfloat162*)(pAh + u) = __nv_bfloat162(h0, h1);          \
                *(__nv_bfloat162*)(pAl + u) = __nv_bfloat162(l0, l1);          \
            }                                                                  \
        }                                                                      \
        _Pragma("unroll")                                                      \
        for (int q = 0; q < 4; q++) {                                          \
            int row = brr + q * 8;                                             \
            __nv_bfloat16* pBh = sm + SBH_OFF + (p) * 8448 + row * 264 + bcc;  \
            __nv_bfloat16* pBl = sm + SBL_OFF + (p) * 8448 + row * 264 + bcc;  \
            float vs[4] = {b4[q].x, b4[q].y, b4[q].z, b4[q].w};                \
            _Pragma("unroll")                                                  \
            for (int u = 0; u < 4; u += 2) {                                   \
                __nv_bfloat16 h0, l0, h1, l1;                                  \
                split_bf16(vs[u], h0, l0);                                     \
                split_bf16(vs[u + 1], h1, l1);                                 \
                *(__nv_bfloat162*)(pBh + u) = __nv_bfloat162(h0, h1);          \
                *(__nv_bfloat162*)(pBl + u) = __nv_bfloat162(l0, l1);          \
            }                                                                  \
        }                                                                      \
    } while (0)

    STORE_TILE(0);
    __syncthreads();

#pragma unroll
    for (int it = 0; it < INC / GBK; it++) {
        int p = it & 1;
        // prefetch next K tile into registers
        if (it < INC / GBK - 1) {
            int k0 = (it + 1) * GBK;
#pragma unroll
            for (int q = 0; q < 2; q++) {
                int gr = brow + ar + q * 64;
                a4[q] = make_float4(0.f, 0.f, 0.f, 0.f);
                if (gr < Nn) a4[q] = *(const float4*)&A[(size_t)gr * INC + k0 + ac];
            }
#pragma unroll
            for (int q = 0; q < 4; q++)
                b4[q] = *(const float4*)&B[(size_t)(k0 + brr + q * 8) * HC + bcc];
        }

        const __nv_bfloat16* bAh = sm + SAH_OFF + p * 5120;
        const __nv_bfloat16* bAl = sm + SAL_OFF + p * 5120;
        const __nv_bfloat16* bBh = sm + SBH_OFF + p * 8448;
        const __nv_bfloat16* bBl = sm + SBL_OFF + p * 8448;
#pragma unroll
        for (int ks = 0; ks < 2; ks++) {
            unsigned Ah[2][4], Al[2][4];
            int akk = ks * 16 + (lane >> 4) * 8;
#pragma unroll
            for (int mt = 0; mt < 2; mt++) {
                int r = wm * 32 + mt * 16 + (lane & 15);
                ldsm4(Ah[mt], bAh + r * 40 + akk);
                ldsm4(Al[mt], bAl + r * 40 + akk);
            }
            int bkr = ks * 16 + ((lane >> 3) & 1) * 8 + (lane & 7);
            // process B in two 32-col halves to bound register pressure
#pragma unroll
            for (int hb = 0; hb < 2; hb++) {
                unsigned Bh[2][4], Bl[2][4];
#pragma unroll
                for (int pp = 0; pp < 2; pp++) {
                    int bnc = wn * 64 + hb * 32 + pp * 16 + (lane >> 4) * 8;
                    ldsm4t(Bh[pp], bBh + bkr * 264 + bnc);
                    ldsm4t(Bl[pp], bBl + bkr * 264 + bnc);
                }
#pragma unroll
                for (int mt = 0; mt < 2; mt++)
#pragma unroll
                    for (int ntl = 0; ntl < 4; ntl++) {
                        int nt = hb * 4 + ntl;
                        int pp = ntl >> 1, i0 = (ntl & 1) * 2;
                        mma16816(acc[mt][nt], Ah[mt], Bh[pp][i0], Bh[pp][i0 + 1]);
                        mma16816(acc[mt][nt], Ah[mt], Bl[pp][i0], Bl[pp][i0 + 1]);
                        mma16816(acc[mt][nt], Al[mt], Bh[pp][i0], Bh[pp][i0 + 1]);
                    }
            }
        }

        if (it < INC / GBK - 1) {
            STORE_TILE(p ^ 1);
            __syncthreads();
        }
    }

    // epilogue: store fp16 directly
#pragma unroll
    for (int mt = 0; mt < 2; mt++) {
        int r0 = brow + wm * 32 + mt * 16 + (lane >> 2);
#pragma unroll
        for (int nt = 0; nt < 8; nt++) {
            int c = wn * 64 + nt * 8 + (lane & 3) * 2;
            if (r0 < Nn) {
                __half2 hv = __floats2half2_rn(acc[mt][nt][0], acc[mt][nt][1]);
                *(__half2*)&g_xhh[(size_t)r0 * HC + c] = hv;
            }
            if (r0 + 8 < Nn) {
                __half2 hv = __floats2half2_rn(acc[mt][nt][2], acc[mt][nt][3]);
                *(__half2*)&g_xhh[(size_t)(r0 + 8) * HC + c] = hv;
            }
        }
    }
}

// ---------------- K4: exclusive scan -> CSR offsets (warp-shuffle) ---------
__global__ void k_scan(int Nn) {
    __shared__ int wsum[32];
    __shared__ int carry;
    int tid = threadIdx.x, lane = tid & 31, wid = tid >> 5;
    if (tid == 0) { carry = 0; g_off[0] = 0; }
    __syncthreads();
    for (int base = 0; base < Nn; base += 1024) {
        int i = base + tid;
        int v = (i < Nn) ? g_cnt[i] : 0;
        int sv = v;
#pragma unroll
        for (int o = 1; o < 32; o <<= 1) {
            int t = __shfl_up_sync(0xFFFFFFFFu, sv, o);
            if (lane >= o) sv += t;
        }
        if (lane == 31) wsum[wid] = sv;
        __syncthreads();
        if (wid == 0) {
            int ws = wsum[lane];
#pragma unroll
            for (int o = 1; o < 32; o <<= 1) {
                int t = __shfl_up_sync(0xFFFFFFFFu, ws, o);
                if (lane >= o) ws += t;
            }
            wsum[lane] = ws;
        }
        __syncthreads();
        int add = carry + (wid > 0 ? wsum[wid - 1] : 0);
        if (i < Nn) g_off[i + 1] = sv + add;
        __syncthreads();
        if (tid == 0) carry += wsum[31];
        __syncthreads();
    }
}

// ---------------- K5: scatter (src, edge id) into dst-sorted order ---------
__global__ void k_scatter(int E) {
    int e = blockIdx.x * blockDim.x + threadIdx.x;
    if (e >= E) return;
    int s = g_edges[e];
    int d = g_edges[E + e];
    int pos = g_off[d] + atomicAdd(&g_fill[d], 1);
    g_sedge[pos] = make_int2(s, e);
}

// ---------------- fp16 4-channel fma -----------------------------------------
__device__ __forceinline__ void fma4(float& a0, float& a1, float& a2, float& a3,
                                     uint2 p, float w) {
    float2 f0 = __half22float2(*(__half2*)&p.x);
    float2 f1 = __half22float2(*(__half2*)&p.y);
    a0 += w * f0.x; a1 += w * f0.y; a2 += w * f1.x; a3 += w * f1.y;
}

// ---------------- K6: 2 warps/node softmax + aggregation + alpha ------------
__global__ __launch_bounds__(256) void k_agg(const float* __restrict__ x,
                                             const float* __restrict__ bias,
                                             float* __restrict__ out,
                                             float* __restrict__ alpha_out,
                                             int Nn, int E) {
    int gw   = (blockIdx.x * blockDim.x + threadIdx.x) >> 5;
    int lane = threadIdx.x & 31;
    int d    = gw >> 1;         // node
    int hf   = gw & 1;          // channel half
    if (d >= Nn) return;
    int cb = hf * 128 + lane * 4;   // 4 channels per lane
    int h  = cb >> 5;               // head

    float adst_h = __ldg(&g_adst[d * NHEAD + h]);

    // self loop
    float e0 = __ldg(&g_asrc[d * NHEAD + h]) + adst_h;
    e0 = (e0 > 0.f) ? e0 : 0.2f * e0;
    float ex = __expf(e0);
    float dn = ex;
    float a0 = 0.f, a1 = 0.f, a2 = 0.f, a3 = 0.f;
    {
        uint2 pd = __ldg((const uint2*)&g_xhh[(size_t)d * HC + cb]);
        fma4(a0, a1, a2, a3, pd, ex);
    }

    int beg = g_off[d], end = g_off[d + 1];
    int j = beg;
    for (; j + 3 < end; j += 4) {
        int2 s0 = __ldg(&g_sedge[j]);
        int2 s1 = __ldg(&g_sedge[j + 1]);
        int2 s2 = __ldg(&g_sedge[j + 2]);
        int2 s3 = __ldg(&g_sedge[j + 3]);
        float e0a = __ldg(&g_asrc[s0.x * NHEAD + h]) + adst_h;
        float e1a = __ldg(&g_asrc[s1.x * NHEAD + h]) + adst_h;
        float e2a = __ldg(&g_asrc[s2.x * NHEAD + h]) + adst_h;
        float e3a = __ldg(&g_asrc[s3.x * NHEAD + h]) + adst_h;
        uint2 p0 = __ldg((const uint2*)&g_xhh[(size_t)s0.x * HC + cb]);
        uint2 p1 = __ldg((const uint2*)&g_xhh[(size_t)s1.x * HC + cb]);
        uint2 p2 = __ldg((const uint2*)&g_xhh[(size_t)s2.x * HC + cb]);
        uint2 p3 = __ldg((const uint2*)&g_xhh[(size_t)s3.x * HC + cb]);
        e0a = (e0a > 0.f) ? e0a : 0.2f * e0a;
        e1a = (e1a > 0.f) ? e1a : 0.2f * e1a;
        e2a = (e2a > 0.f) ? e2a : 0.2f * e2a;
        e3a = (e3a > 0.f) ? e3a : 0.2f * e3a;
        float w0 = __expf(e0a), w1 = __expf(e1a);
        float w2 = __expf(e2a), w3 = __expf(e3a);
        dn += (w0 + w1) + (w2 + w3);
        fma4(a0, a1, a2, a3, p0, w0);
        fma4(a0, a1, a2, a3, p1, w1);
        fma4(a0, a1, a2, a3, p2, w2);
        fma4(a0, a1, a2, a3, p3, w3);
    }
    for (; j < end; j++) {
        int2 sa = __ldg(&g_sedge[j]);
        float ea = __ldg(&g_asrc[sa.x * NHEAD + h]) + adst_h;
        ea = (ea > 0.f) ? ea : 0.2f * ea;
        float wa = __expf(ea);
        dn += wa;
        uint2 pa = __ldg((const uint2*)&g_xhh[(size_t)sa.x * HC + cb]);
        fma4(a0, a1, a2, a3, pa, wa);
    }

    float inv = 1.f / (dn + 1e-16f);
    float4 xb = __ldg((const float4*)&x[(size_t)d * HC + cb]);
    float4 bb = __ldg((const float4*)&bias[cb]);
    float4 o  = make_float4(a0 * inv + xb.x + bb.x, a1 * inv + xb.y + bb.y,
                            a2 * inv + xb.z + bb.z, a3 * inv + xb.w + bb.w);
    *(float4*)&out[(size_t)d * HC + cb] = o;

    // ---- alpha pass: this warp covers its 4 heads; 8 edges in flight ----
    if (alpha_out) {
        int hh = hf * 4 + (lane & 3);
        float dnh = __shfl_sync(0xFFFFFFFFu, dn, (lane & 3) * 8) + 1e-16f;
        float adst8 = __ldg(&g_adst[d * NHEAD + hh]);
        if (lane < 4) {
            float es = __ldg(&g_asrc[d * NHEAD + hh]) + adst8;
            es = (es > 0.f) ? es : 0.2f * es;
            alpha_out[(size_t)(E + d) * NHEAD + hh] = __expf(es) / dnh;
        }
        for (int jj = beg + (lane >> 2); jj < end; jj += 8) {
            int2 se = __ldg(&g_sedge[jj]);
            float e = __ldg(&g_asrc[se.x * NHEAD + hh]) + adst8;
            e = (e > 0.f) ? e : 0.2f * e;
            alpha_out[(size_t)se.y * NHEAD + hh] = __expf(e) / dnh;
        }
    }
}

// ---------------- host launcher ---------------------------------------------
extern "C" void kernel_launch(void* const* d_in, const int* in_sizes, int n_in,
                              void* d_out, int out_size) {
    const float* x       = (const float*)d_in[0];
    const void*  ei      = d_in[1];
    const float* W       = (const float*)d_in[2];
    const float* att_src = (const float*)d_in[3];
    const float* att_dst = (const float*)d_in[4];
    const float* bias    = (const float*)d_in[5];

    int Nn   = in_sizes[0] / INC;
    int E    = in_sizes[1] / 2;
    int Etot = E + Nn;

    float* out = (float*)d_out;
    float* alpha_out = nullptr;
    if ((long long)out_size >= (long long)Nn * HC + (long long)Etot * NHEAD)
        alpha_out = out + (size_t)Nn * HC;

    // one-time host objects (no device memory involved)
    static cudaStream_t s1 = nullptr;
    static cudaEvent_t  evFork = nullptr, evJoin = nullptr;
    static int          inited = 0;
    if (!inited) {
        cudaStreamCreateWithFlags(&s1, cudaStreamNonBlocking);
        cudaEventCreateWithFlags(&evFork, cudaEventDisableTiming);
        cudaEventCreateWithFlags(&evJoin, cudaEventDisableTiming);
        cudaFuncSetAttribute(k_gemm, cudaFuncAttributeMaxDynamicSharedMemorySize,
                             SMEM_ELEMS * 2);
        inited = 1;
    }

    // fork: branch stream s1 runs the GEMM; main stream runs logits + CSR
    cudaEventRecord(evFork, 0);
    cudaStreamWaitEvent(s1, evFork, 0);

    // --- branch A (s1): projection GEMM only ---
    k_gemm<<<(Nn + GBM - 1) / GBM, 512, SMEM_ELEMS * 2, s1>>>(x, W, Nn);

    // --- branch B (main stream): folded logits + edge conversion + CSR ---
    k_prew<<<16, 256>>>(W, att_src, att_dst);
    k_lg<<<(Nn * 32 + 255) / 256, 256>>>(x, Nn);
    k_detect<<<1, 256>>>((const int*)ei, 16384);
    k_zero<<<(Nn + 255) / 256, 256>>>(Nn);
    k_convert<<<(2 * E + 255) / 256, 256>>>(ei, 2 * E, E);
    k_scan<<<1, 1024>>>(Nn);
    k_scatter<<<(E + 255) / 256, 256>>>(E);

    // join: main stream waits for branch A
    cudaEventRecord(evJoin, s1);
    cudaStreamWaitEvent(0, evJoin, 0);

    // fused softmax + aggregation + residual + bias + alpha (no atomics)
    k_agg<<<(Nn * 64 + 255) / 256, 256>>>(x, bias, out, alpha_out, Nn, E);
}

// round 15
// speedup vs baseline: 1.3294x; 1.3294x over previous
#include <cuda_runtime.h>
#include <cuda_bf16.h>
#include <cuda_fp16.h>

// Problem constants (fixed shapes from the reference)
#define NMAX 50000
#define EMAX 800000
#define INC  256
#define NHEAD 8
#define CH   32
#define HC   256   // NHEAD*CH

// ---------------- scratch (static device globals; no allocs allowed) -------
__device__ __half   g_xhh[NMAX * HC];           // projected features, fp16
__device__ float    g_asrc[NMAX * NHEAD];       // per-node src logits
__device__ float    g_adst[NMAX * NHEAD];       // per-node dst logits
__device__ int      g_edges[2 * EMAX];          // converted int32 edge index
__device__ int      g_cnt[NMAX];                // in-degree histogram
__device__ int      g_fill[NMAX];               // scatter fill counters
__device__ int      g_off[NMAX + 1];            // CSR offsets
__device__ int2     g_sedge[EMAX];              // (src, orig edge id) dst-sorted
__device__ int      g_is64;

// ---------------- K0: detect int64 vs int32 edge_index ---------------------
__global__ void k_detect(const int* __restrict__ p, int n_words) {
    __shared__ int s;
    if (threadIdx.x == 0) s = 0;
    __syncthreads();
    int acc = 0;
    for (int i = 1 + 2 * (int)threadIdx.x; i < n_words; i += 2 * blockDim.x)
        acc |= p[i];
    if (acc) atomicOr(&s, 1);
    __syncthreads();
    if (threadIdx.x == 0) g_is64 = (s == 0) ? 1 : 0;
}

// ---------------- K0b: zero histogram + fill counters ----------------------
__global__ void k_zero(int Nn) {
    int i = blockIdx.x * blockDim.x + threadIdx.x;
    if (i < Nn) { g_cnt[i] = 0; g_fill[i] = 0; }
}

// ---------------- K1: convert edge index to int32 + dst histogram ----------
__global__ void k_convert(const void* __restrict__ p, int twoE, int E) {
    int i = blockIdx.x * blockDim.x + threadIdx.x;
    if (i >= twoE) return;
    int v;
    if (g_is64) v = (int)((const long long*)p)[i];
    else        v = ((const int*)p)[i];
    g_edges[i] = v;
    if (i >= E) atomicAdd(&g_cnt[v], 1);   // dst half -> in-degree histogram
}

// ---------------- MMA helpers ----------------------------------------------
__device__ __forceinline__ void ldsm4(unsigned r[4], const void* p) {
    unsigned a = (unsigned)__cvta_generic_to_shared(p);
    asm volatile("ldmatrix.sync.aligned.m8n8.x4.shared.b16 {%0,%1,%2,%3}, [%4];"
                 : "=r"(r[0]), "=r"(r[1]), "=r"(r[2]), "=r"(r[3]) : "r"(a));
}
__device__ __forceinline__ void ldsm4t(unsigned r[4], const void* p) {
    unsigned a = (unsigned)__cvta_generic_to_shared(p);
    asm volatile("ldmatrix.sync.aligned.m8n8.x4.trans.shared.b16 {%0,%1,%2,%3}, [%4];"
                 : "=r"(r[0]), "=r"(r[1]), "=r"(r[2]), "=r"(r[3]) : "r"(a));
}
__device__ __forceinline__ void mma16816(float c[4], const unsigned a[4],
                                         unsigned b0, unsigned b1) {
    asm volatile(
        "mma.sync.aligned.m16n8k16.row.col.f32.bf16.bf16.f32 "
        "{%0,%1,%2,%3}, {%4,%5,%6,%7}, {%8,%9}, {%0,%1,%2,%3};"
        : "+f"(c[0]), "+f"(c[1]), "+f"(c[2]), "+f"(c[3])
        : "r"(a[0]), "r"(a[1]), "r"(a[2]), "r"(a[3]), "r"(b0), "r"(b1));
}
__device__ __forceinline__ void split_bf16(float v, __nv_bfloat16& h, __nv_bfloat16& l) {
    h = __float2bfloat16(v);
    l = __float2bfloat16(v - __bfloat162float(h));
}

// ---------------- K2: xh = x @ W  -- CTA 128x256, 512 thr, bf16 split ------
// 16 warps as 4(M) x 4(N); warp tile 32x64. A read ONCE from DRAM.
// acc = Ah*Bh + Ah*Bl + Al*Bh
#define GBM 128
#define GBK 32
// dynamic smem element offsets (bf16 elements)
#define SAH_OFF 0              // [2][128][40]
#define SAL_OFF 10240
#define SBH_OFF 20480          // [2][32][264]
#define SBL_OFF 37376
#define SMEM_ELEMS 54272       // * 2B = 108544 bytes

__global__ __launch_bounds__(512, 1) void k_gemm(const float* __restrict__ A,
                                                 const float* __restrict__ B,
                                                 int Nn) {
    extern __shared__ __nv_bfloat16 sm[];

    int tid  = threadIdx.x;
    int lane = tid & 31;
    int warp = tid >> 5;
    int wm = warp & 3, wn = warp >> 2;   // 4 x 4 warp grid
    int brow = blockIdx.x * GBM;

    float acc[2][8][4];
#pragma unroll
    for (int i = 0; i < 2; i++)
#pragma unroll
        for (int j = 0; j < 8; j++)
#pragma unroll
            for (int k = 0; k < 4; k++) acc[i][j][k] = 0.f;

    // loader coordinates
    int ar  = tid >> 3;            // A row 0..63 (+q*64)
    int ac  = (tid & 7) * 4;       // A col 0..28
    int brr = tid >> 6;            // B row 0..7 (+q*8)
    int bcc = (tid & 63) * 4;      // B col 0..252

    float4 a4[2], b4[4];

    // prologue: load k0 = 0
#pragma unroll
    for (int q = 0; q < 2; q++) {
        int gr = brow + ar + q * 64;
        a4[q] = make_float4(0.f, 0.f, 0.f, 0.f);
        if (gr < Nn) a4[q] = *(const float4*)&A[(size_t)gr * INC + ac];
    }
#pragma unroll
    for (int q = 0; q < 4; q++)
        b4[q] = *(const float4*)&B[(size_t)(brr + q * 8) * HC + bcc];

#define STORE_TILE(p)                                                          \
    do {                                                                       \
        _Pragma("unroll")                                                      \
        for (int q = 0; q < 2; q++) {                                          \
            int row = ar + q * 64;                                             \
            __nv_bfloat16* pAh = sm + SAH_OFF + (p) * 5120 + row * 40 + ac;    \
            __nv_bfloat16* pAl = sm + SAL_OFF + (p) * 5120 + row * 40 + ac;    \
            float vs[4] = {a4[q].x, a4[q].y, a4[q].z, a4[q].w};                \
            _Pragma("unroll")                                                  \
            for (int u = 0; u < 4; u += 2) {                                   \
                __nv_bfloat16 h0, l0, h1, l1;                                  \
                split_bf16(vs[u], h0, l0);                                     \
                split_bf16(vs[u + 1], h1, l1);                                 \
                *(__nv_bfloat162*)(pAh + u) = __nv_bfloat162(h0, h1);          \
                *(__nv_bfloat162*)(pAl + u) = __nv_bfloat162(l0, l1);          \
            }                                                                  \
        }                                                                      \
        _Pragma("unroll")                                                      \
        for (int q = 0; q < 4; q++) {                                          \
            int row = brr + q * 8;                                             \
            __nv_bfloat16* pBh = sm + SBH_OFF + (p) * 8448 + row * 264 + bcc;  \
            __nv_bfloat16* pBl = sm + SBL_OFF + (p) * 8448 + row * 264 + bcc;  \
            float vs[4] = {b4[q].x, b4[q].y, b4[q].z, b4[q].w};                \
            _Pragma("unroll")                                                  \
            for (int u = 0; u < 4; u += 2) {                                   \
                __nv_bfloat16 h0, l0, h1, l1;                                  \
                split_bf16(vs[u], h0, l0);                                     \
                split_bf16(vs[u + 1], h1, l1);                                 \
                *(__nv_bfloat162*)(pBh + u) = __nv_bfloat162(h0, h1);          \
                *(__nv_bfloat162*)(pBl + u) = __nv_bfloat162(l0, l1);          \
            }                                                                  \
        }                                                                      \
    } while (0)

    STORE_TILE(0);
    __syncthreads();

#pragma unroll
    for (int it = 0; it < INC / GBK; it++) {
        int p = it & 1;
        // prefetch next K tile into registers
        if (it < INC / GBK - 1) {
            int k0 = (it + 1) * GBK;
#pragma unroll
            for (int q = 0; q < 2; q++) {
                int gr = brow + ar + q * 64;
                a4[q] = make_float4(0.f, 0.f, 0.f, 0.f);
                if (gr < Nn) a4[q] = *(const float4*)&A[(size_t)gr * INC + k0 + ac];
            }
#pragma unroll
            for (int q = 0; q < 4; q++)
                b4[q] = *(const float4*)&B[(size_t)(k0 + brr + q * 8) * HC + bcc];
        }

        const __nv_bfloat16* bAh = sm + SAH_OFF + p * 5120;
        const __nv_bfloat16* bAl = sm + SAL_OFF + p * 5120;
        const __nv_bfloat16* bBh = sm + SBH_OFF + p * 8448;
        const __nv_bfloat16* bBl = sm + SBL_OFF + p * 8448;
#pragma unroll
        for (int ks = 0; ks < 2; ks++) {
            unsigned Ah[2][4], Al[2][4];
            int akk = ks * 16 + (lane >> 4) * 8;
#pragma unroll
            for (int mt = 0; mt < 2; mt++) {
                int r = wm * 32 + mt * 16 + (lane & 15);
                ldsm4(Ah[mt], bAh + r * 40 + akk);
                ldsm4(Al[mt], bAl + r * 40 + akk);
            }
            int bkr = ks * 16 + ((lane >> 3) & 1) * 8 + (lane & 7);
            // process B in two 32-col halves to bound register pressure
#pragma unroll
            for (int hb = 0; hb < 2; hb++) {
                unsigned Bh[2][4], Bl[2][4];
#pragma unroll
                for (int pp = 0; pp < 2; pp++) {
                    int bnc = wn * 64 + hb * 32 + pp * 16 + (lane >> 4) * 8;
                    ldsm4t(Bh[pp], bBh + bkr * 264 + bnc);
                    ldsm4t(Bl[pp], bBl + bkr * 264 + bnc);
                }
#pragma unroll
                for (int mt = 0; mt < 2; mt++)
#pragma unroll
                    for (int ntl = 0; ntl < 4; ntl++) {
                        int nt = hb * 4 + ntl;
                        int pp = ntl >> 1, i0 = (ntl & 1) * 2;
                        mma16816(acc[mt][nt], Ah[mt], Bh[pp][i0], Bh[pp][i0 + 1]);
                        mma16816(acc[mt][nt], Ah[mt], Bl[pp][i0], Bl[pp][i0 + 1]);
                        mma16816(acc[mt][nt], Al[mt], Bh[pp][i0], Bh[pp][i0 + 1]);
                    }
            }
        }

        if (it < INC / GBK - 1) {
            STORE_TILE(p ^ 1);
            __syncthreads();
        }
    }

    // epilogue: store fp16 directly
#pragma unroll
    for (int mt = 0; mt < 2; mt++) {
        int r0 = brow + wm * 32 + mt * 16 + (lane >> 2);
#pragma unroll
        for (int nt = 0; nt < 8; nt++) {
            int c = wn * 64 + nt * 8 + (lane & 3) * 2;
            if (r0 < Nn) {
                __half2 hv = __floats2half2_rn(acc[mt][nt][0], acc[mt][nt][1]);
                *(__half2*)&g_xhh[(size_t)r0 * HC + c] = hv;
            }
            if (r0 + 8 < Nn) {
                __half2 hv = __floats2half2_rn(acc[mt][nt][2], acc[mt][nt][3]);
                *(__half2*)&g_xhh[(size_t)(r0 + 8) * HC + c] = hv;
            }
        }
    }
}

// ---------------- K3: logits from fp16 features (warp per node) ------------
__global__ void k_logits(const float* __restrict__ att_src,
                         const float* __restrict__ att_dst, int Nn) {
    int w    = (blockIdx.x * blockDim.x + threadIdx.x) >> 5;
    int lane = threadIdx.x & 31;
    if (w >= Nn) return;
    int cb = lane * 8;
    uint4 pk = *(const uint4*)&g_xhh[(size_t)w * HC + cb];
    float2 f0 = __half22float2(*(__half2*)&pk.x);
    float2 f1 = __half22float2(*(__half2*)&pk.y);
    float2 f2 = __half22float2(*(__half2*)&pk.z);
    float2 f3 = __half22float2(*(__half2*)&pk.w);

    float4 s0 = *(const float4*)&att_src[cb];
    float4 s1 = *(const float4*)&att_src[cb + 4];
    float4 d0 = *(const float4*)&att_dst[cb];
    float4 d1 = *(const float4*)&att_dst[cb + 4];
    float s = f0.x * s0.x + f0.y * s0.y + f1.x * s0.z + f1.y * s0.w
            + f2.x * s1.x + f2.y * s1.y + f3.x * s1.z + f3.y * s1.w;
    float d = f0.x * d0.x + f0.y * d0.y + f1.x * d0.z + f1.y * d0.w
            + f2.x * d1.x + f2.y * d1.y + f3.x * d1.z + f3.y * d1.w;
    s += __shfl_xor_sync(0xFFFFFFFFu, s, 1);
    s += __shfl_xor_sync(0xFFFFFFFFu, s, 2);
    d += __shfl_xor_sync(0xFFFFFFFFu, d, 1);
    d += __shfl_xor_sync(0xFFFFFFFFu, d, 2);
    if ((lane & 3) == 0) {
        g_asrc[w * NHEAD + (lane >> 2)] = s;
        g_adst[w * NHEAD + (lane >> 2)] = d;
    }
}

// ---------------- K4: exclusive scan -> CSR offsets (warp-shuffle) ---------
__global__ void k_scan(int Nn) {
    __shared__ int wsum[32];
    __shared__ int carry;
    int tid = threadIdx.x, lane = tid & 31, wid = tid >> 5;
    if (tid == 0) { carry = 0; g_off[0] = 0; }
    __syncthreads();
    for (int base = 0; base < Nn; base += 1024) {
        int i = base + tid;
        int v = (i < Nn) ? g_cnt[i] : 0;
        int sv = v;
#pragma unroll
        for (int o = 1; o < 32; o <<= 1) {
            int t = __shfl_up_sync(0xFFFFFFFFu, sv, o);
            if (lane >= o) sv += t;
        }
        if (lane == 31) wsum[wid] = sv;
        __syncthreads();
        if (wid == 0) {
            int ws = wsum[lane];
#pragma unroll
            for (int o = 1; o < 32; o <<= 1) {
                int t = __shfl_up_sync(0xFFFFFFFFu, ws, o);
                if (lane >= o) ws += t;
            }
            wsum[lane] = ws;
        }
        __syncthreads();
        int add = carry + (wid > 0 ? wsum[wid - 1] : 0);
        if (i < Nn) g_off[i + 1] = sv + add;
        __syncthreads();
        if (tid == 0) carry += wsum[31];
        __syncthreads();
    }
}

// ---------------- K5: scatter (src, edge id) into dst-sorted order ---------
__global__ void k_scatter(int E) {
    int e = blockIdx.x * blockDim.x + threadIdx.x;
    if (e >= E) return;
    int s = g_edges[e];
    int d = g_edges[E + e];
    int pos = g_off[d] + atomicAdd(&g_fill[d], 1);
    g_sedge[pos] = make_int2(s, e);
}

// ---------------- fp16 4-channel fma -----------------------------------------
__device__ __forceinline__ void fma4(float& a0, float& a1, float& a2, float& a3,
                                     uint2 p, float w) {
    float2 f0 = __half22float2(*(__half2*)&p.x);
    float2 f1 = __half22float2(*(__half2*)&p.y);
    a0 += w * f0.x; a1 += w * f0.y; a2 += w * f1.x; a3 += w * f1.y;
}

// ---------------- K6: 2 warps/node softmax + aggregation + alpha ------------
__global__ __launch_bounds__(256) void k_agg(const float* __restrict__ x,
                                             const float* __restrict__ bias,
                                             float* __restrict__ out,
                                             float* __restrict__ alpha_out,
                                             int Nn, int E) {
    int gw   = (blockIdx.x * blockDim.x + threadIdx.x) >> 5;
    int lane = threadIdx.x & 31;
    int d    = gw >> 1;         // node
    int hf   = gw & 1;          // channel half
    if (d >= Nn) return;
    int cb = hf * 128 + lane * 4;   // 4 channels per lane
    int h  = cb >> 5;               // head

    float adst_h = __ldg(&g_adst[d * NHEAD + h]);

    // self loop
    float e0 = __ldg(&g_asrc[d * NHEAD + h]) + adst_h;
    e0 = (e0 > 0.f) ? e0 : 0.2f * e0;
    float ex = __expf(e0);
    float dn = ex;
    float a0 = 0.f, a1 = 0.f, a2 = 0.f, a3 = 0.f;
    {
        uint2 pd = __ldg((const uint2*)&g_xhh[(size_t)d * HC + cb]);
        fma4(a0, a1, a2, a3, pd, ex);
    }

    int beg = g_off[d], end = g_off[d + 1];
    int j = beg;
    for (; j + 3 < end; j += 4) {
        int2 s0 = __ldg(&g_sedge[j]);
        int2 s1 = __ldg(&g_sedge[j + 1]);
        int2 s2 = __ldg(&g_sedge[j + 2]);
        int2 s3 = __ldg(&g_sedge[j + 3]);
        float e0a = __ldg(&g_asrc[s0.x * NHEAD + h]) + adst_h;
        float e1a = __ldg(&g_asrc[s1.x * NHEAD + h]) + adst_h;
        float e2a = __ldg(&g_asrc[s2.x * NHEAD + h]) + adst_h;
        float e3a = __ldg(&g_asrc[s3.x * NHEAD + h]) + adst_h;
        uint2 p0 = __ldg((const uint2*)&g_xhh[(size_t)s0.x * HC + cb]);
        uint2 p1 = __ldg((const uint2*)&g_xhh[(size_t)s1.x * HC + cb]);
        uint2 p2 = __ldg((const uint2*)&g_xhh[(size_t)s2.x * HC + cb]);
        uint2 p3 = __ldg((const uint2*)&g_xhh[(size_t)s3.x * HC + cb]);
        e0a = (e0a > 0.f) ? e0a : 0.2f * e0a;
        e1a = (e1a > 0.f) ? e1a : 0.2f * e1a;
        e2a = (e2a > 0.f) ? e2a : 0.2f * e2a;
        e3a = (e3a > 0.f) ? e3a : 0.2f * e3a;
        float w0 = __expf(e0a), w1 = __expf(e1a);
        float w2 = __expf(e2a), w3 = __expf(e3a);
        dn += (w0 + w1) + (w2 + w3);
        fma4(a0, a1, a2, a3, p0, w0);
        fma4(a0, a1, a2, a3, p1, w1);
        fma4(a0, a1, a2, a3, p2, w2);
        fma4(a0, a1, a2, a3, p3, w3);
    }
    for (; j < end; j++) {
        int2 sa = __ldg(&g_sedge[j]);
        float ea = __ldg(&g_asrc[sa.x * NHEAD + h]) + adst_h;
        ea = (ea > 0.f) ? ea : 0.2f * ea;
        float wa = __expf(ea);
        dn += wa;
        uint2 pa = __ldg((const uint2*)&g_xhh[(size_t)sa.x * HC + cb]);
        fma4(a0, a1, a2, a3, pa, wa);
    }

    float inv = 1.f / (dn + 1e-16f);
    float4 xb = __ldg((const float4*)&x[(size_t)d * HC + cb]);
    float4 bb = __ldg((const float4*)&bias[cb]);
    float4 o  = make_float4(a0 * inv + xb.x + bb.x, a1 * inv + xb.y + bb.y,
                            a2 * inv + xb.z + bb.z, a3 * inv + xb.w + bb.w);
    *(float4*)&out[(size_t)d * HC + cb] = o;

    // ---- alpha pass: this warp covers its 4 heads; 8 edges in flight ----
    if (alpha_out) {
        int hh = hf * 4 + (lane & 3);
        float dnh = __shfl_sync(0xFFFFFFFFu, dn, (lane & 3) * 8) + 1e-16f;
        float adst8 = __ldg(&g_adst[d * NHEAD + hh]);
        if (lane < 4) {
            float es = __ldg(&g_asrc[d * NHEAD + hh]) + adst8;
            es = (es > 0.f) ? es : 0.2f * es;
            alpha_out[(size_t)(E + d) * NHEAD + hh] = __expf(es) / dnh;
        }
        for (int jj = beg + (lane >> 2); jj < end; jj += 8) {
            int2 se = __ldg(&g_sedge[jj]);
            float e = __ldg(&g_asrc[se.x * NHEAD + hh]) + adst8;
            e = (e > 0.f) ? e : 0.2f * e;
            alpha_out[(size_t)se.y * NHEAD + hh] = __expf(e) / dnh;
        }
    }
}

// ---------------- host launcher ---------------------------------------------
extern "C" void kernel_launch(void* const* d_in, const int* in_sizes, int n_in,
                              void* d_out, int out_size) {
    const float* x       = (const float*)d_in[0];
    const void*  ei      = d_in[1];
    const float* W       = (const float*)d_in[2];
    const float* att_src = (const float*)d_in[3];
    const float* att_dst = (const float*)d_in[4];
    const float* bias    = (const float*)d_in[5];

    int Nn   = in_sizes[0] / INC;
    int E    = in_sizes[1] / 2;
    int Etot = E + Nn;

    float* out = (float*)d_out;
    float* alpha_out = nullptr;
    if ((long long)out_size >= (long long)Nn * HC + (long long)Etot * NHEAD)
        alpha_out = out + (size_t)Nn * HC;

    // one-time host objects (no device memory involved)
    static cudaStream_t s1 = nullptr;
    static cudaEvent_t  evFork = nullptr, evJoin = nullptr;
    static int          inited = 0;
    if (!inited) {
        cudaStreamCreateWithFlags(&s1, cudaStreamNonBlocking);
        cudaEventCreateWithFlags(&evFork, cudaEventDisableTiming);
        cudaEventCreateWithFlags(&evJoin, cudaEventDisableTiming);
        cudaFuncSetAttribute(k_gemm, cudaFuncAttributeMaxDynamicSharedMemorySize,
                             SMEM_ELEMS * 2);
        inited = 1;
    }

    // fork: branch stream s1 runs GEMM + logits, main stream builds CSR
    cudaEventRecord(evFork, 0);
    cudaStreamWaitEvent(s1, evFork, 0);

    // --- branch A (s1): projection GEMM + per-node logits ---
    k_gemm<<<(Nn + GBM - 1) / GBM, 512, SMEM_ELEMS * 2, s1>>>(x, W, Nn);
    k_logits<<<(Nn * 32 + 255) / 256, 256, 0, s1>>>(att_src, att_dst, Nn);

    // --- branch B (main stream): edge conversion + CSR build ---
    k_detect<<<1, 256>>>((const int*)ei, 16384);
    k_zero<<<(Nn + 255) / 256, 256>>>(Nn);
    k_convert<<<(2 * E + 255) / 256, 256>>>(ei, 2 * E, E);
    k_scan<<<1, 1024>>>(Nn);
    k_scatter<<<(E + 255) / 256, 256>>>(E);

    // join: main stream waits for branch A
    cudaEventRecord(evJoin, s1);
    cudaStreamWaitEvent(0, evJoin, 0);

    // fused softmax + aggregation + residual + bias + alpha (no atomics)
    k_agg<<<(Nn * 64 + 255) / 256, 256>>>(x, bias, out, alpha_out, Nn, E);
}